// round 13
// baseline (speedup 1.0000x reference)
#include <cuda_runtime.h>
#include <cstdint>

#define Bn 16
#define Tn 256
#define Cn 6
#define En 512
#define Hn 8
#define HD 64
#define NTOK (Bn*Tn*Cn)      // 24576
#define NHEADS (Bn*Hn*Cn)    // 768

// ---- device-global scratch (no allocations allowed) ----
// g_xr, g_wr: k-interleaved (perfect-shuffle per 8-block) tf32.
// g_q/g_k/g_v/g_y: plain layout, tf32-rounded values.
__device__ float g_q[(size_t)NHEADS * Tn * HD];
__device__ float g_k[(size_t)NHEADS * Tn * HD];
__device__ float g_v[(size_t)NHEADS * Tn * HD];
__device__ float g_y[(size_t)NTOK * En];
__device__ float g_xr[(size_t)NTOK * En];
__device__ float g_wr[(size_t)4 * En * En];

// ---------------------------------------------------------------------------
__device__ __forceinline__ float tf32r(float x) {
    uint32_t u;
    asm("cvt.rna.tf32.f32 %0, %1;" : "=r"(u) : "f"(x));
    return __uint_as_float(u);
}

__device__ __forceinline__ void cpasync16(void* smem_dst, const void* gsrc) {
    uint32_t s = (uint32_t)__cvta_generic_to_shared(smem_dst);
    asm volatile("cp.async.ca.shared.global [%0], [%1], 16;\n" :: "r"(s), "l"(gsrc));
}

__device__ __forceinline__ void mma_tf32(float c[4], const uint32_t a[4], const uint32_t b[2]) {
    asm volatile(
        "mma.sync.aligned.m16n8k8.row.col.f32.tf32.tf32.f32 "
        "{%0,%1,%2,%3}, {%4,%5,%6,%7}, {%8,%9}, {%0,%1,%2,%3};"
        : "+f"(c[0]), "+f"(c[1]), "+f"(c[2]), "+f"(c[3])
        : "r"(a[0]), "r"(a[1]), "r"(a[2]), "r"(a[3]), "r"(b[0]), "r"(b[1]));
}

// ---------------------------------------------------------------------------
// Prepass: round to tf32 AND perfect-shuffle each 8-float k-block:
//   out[8b + 0..7] = in[8b + {0,4,1,5,2,6,3,7}]
// ---------------------------------------------------------------------------
__device__ __forceinline__ void shuffle_store8(float* dst, float4 lo, float4 hi) {
    float4 o0, o1;
    o0.x = tf32r(lo.x); o0.y = tf32r(hi.x); o0.z = tf32r(lo.y); o0.w = tf32r(hi.y);
    o1.x = tf32r(lo.z); o1.y = tf32r(hi.z); o1.z = tf32r(lo.w); o1.w = tf32r(hi.w);
    *(float4*)dst       = o0;
    *(float4*)(dst + 4) = o1;
}

#define NX8 (NTOK * En / 8)          // 1572864 x-blocks
#define NW8 (4 * En * En / 8)        // 131072 w-blocks

__global__ void round_all_kernel(const float* __restrict__ x,
                                 const float* __restrict__ Wq, const float* __restrict__ Wk,
                                 const float* __restrict__ Wv, const float* __restrict__ Wp) {
    int i = blockIdx.x * 256 + threadIdx.x;
    if (i < NX8) {
        float4 lo = ((const float4*)x)[i * 2];
        float4 hi = ((const float4*)x)[i * 2 + 1];
        shuffle_store8(g_xr + (size_t)i * 8, lo, hi);
    } else {
        int j = i - NX8;
        int w = j >> 15;
        int off = j & 32767;
        const float* src = (w == 0) ? Wq : (w == 1) ? Wk : (w == 2) ? Wv : Wp;
        float4 lo = ((const float4*)src)[off * 2];
        float4 hi = ((const float4*)src)[off * 2 + 1];
        shuffle_store8(g_wr + (size_t)j * 8, lo, hi);
    }
}

// ---------------------------------------------------------------------------
// GEMM cores. 128x128 CTA tile, 8 warps (2M x 4N), warp tile 64x32, BK=16,
// 3-stage cp.async ring, ONE __syncthreads per k-iteration.
//  - interleaved operands: smem stride 24 (==8 mod 32), LDS.64 frags.
//  - plain operands:       smem stride 20, LDS.32 frags.
// ---------------------------------------------------------------------------
#define SSI 24     // interleaved stride
#define SSP 20     // plain stride
#define BK  16
#define NK  (En / BK)   // 32

__device__ __forceinline__ void load_tile_s(float* dst, const float* gsrc,
                                            int stride, int k0, int tid) {
    #pragma unroll
    for (int it = 0; it < 2; it++) {
        int idx = it * 256 + tid;          // 0..511
        int m   = idx >> 2;
        int kc  = (idx & 3) * 4;
        cpasync16(dst + m * stride + kc, gsrc + (size_t)m * En + k0 + kc);
    }
}

// Both operands interleaved (qkv).
__device__ __forceinline__ void compute_tile_ii(const float* As, const float* Bs,
                                                float acc[4][4][4],
                                                int wm, int wn, int gr, int ctl) {
    #pragma unroll
    for (int g2 = 0; g2 < 2; g2++) {
        const int ko = g2 * 8 + 2 * ctl;
        uint32_t a[4][4], b[4][2];
        #pragma unroll
        for (int mi = 0; mi < 4; mi++) {
            const float* p = As + (wm * 64 + mi * 16 + gr) * SSI + ko;
            float2 lo = *(const float2*)p;
            float2 hi = *(const float2*)(p + 8 * SSI);
            a[mi][0] = __float_as_uint(lo.x);
            a[mi][2] = __float_as_uint(lo.y);
            a[mi][1] = __float_as_uint(hi.x);
            a[mi][3] = __float_as_uint(hi.y);
        }
        #pragma unroll
        for (int ni = 0; ni < 4; ni++) {
            const float* p = Bs + (wn * 32 + ni * 8 + gr) * SSI + ko;
            float2 v = *(const float2*)p;
            b[ni][0] = __float_as_uint(v.x);
            b[ni][1] = __float_as_uint(v.y);
        }
        #pragma unroll
        for (int mi = 0; mi < 4; mi++)
            #pragma unroll
            for (int ni = 0; ni < 4; ni++)
                mma_tf32(acc[mi][ni], a[mi], b[ni]);
    }
}

// A plain, B interleaved (proj).
__device__ __forceinline__ void compute_tile_pi(const float* As, const float* Bs,
                                                float acc[4][4][4],
                                                int wm, int wn, int gr, int ctl) {
    #pragma unroll
    for (int g2 = 0; g2 < 2; g2++) {
        uint32_t a[4][4], b[4][2];
        #pragma unroll
        for (int mi = 0; mi < 4; mi++) {
            const float* p = As + (wm * 64 + mi * 16 + gr) * SSP + g2 * 8 + ctl;
            a[mi][0] = __float_as_uint(p[0]);
            a[mi][1] = __float_as_uint(p[8 * SSP]);
            a[mi][2] = __float_as_uint(p[4]);
            a[mi][3] = __float_as_uint(p[8 * SSP + 4]);
        }
        #pragma unroll
        for (int ni = 0; ni < 4; ni++) {
            const float* p = Bs + (wn * 32 + ni * 8 + gr) * SSI + g2 * 8 + 2 * ctl;
            float2 v = *(const float2*)p;
            b[ni][0] = __float_as_uint(v.x);
            b[ni][1] = __float_as_uint(v.y);
        }
        #pragma unroll
        for (int mi = 0; mi < 4; mi++)
            #pragma unroll
            for (int ni = 0; ni < 4; ni++)
                mma_tf32(acc[mi][ni], a[mi], b[ni]);
    }
}

// 3-stage ring mainloop: per iteration  wait -> barrier -> issue(kt+2) -> compute(kt).
// Overwrite safety: loads for stage kt+2 (buffer (kt+2)%3 == (kt-1)%3) are issued
// only after barrier(kt), which all warps reach only after compute(kt-1) finished.
#define GEMM_MAINLOOP3(gA, gB, SA, SB, CT, AsP, BsP)                           \
    load_tile_s(AsP, gA, SA, 0, tid);                                          \
    load_tile_s(BsP, gB, SB, 0, tid);                                          \
    asm volatile("cp.async.commit_group;\n" ::);                               \
    load_tile_s(AsP + 128 * SA, gA, SA, BK, tid);                              \
    load_tile_s(BsP + 128 * SB, gB, SB, BK, tid);                              \
    asm volatile("cp.async.commit_group;\n" ::);                               \
    _Pragma("unroll 1")                                                        \
    for (int kt = 0; kt < NK; kt++) {                                          \
        if (kt == NK - 1) asm volatile("cp.async.wait_group 0;\n" ::);         \
        else              asm volatile("cp.async.wait_group 1;\n" ::);         \
        __syncthreads();                                                       \
        if (kt + 2 < NK) {                                                     \
            int st = kt + 2; st = (st >= 3) ? ((st >= 6) ? st % 3 : st - 3) : st; \
            load_tile_s(AsP + st * 128 * SA, gA, SA, (kt + 2) * BK, tid);      \
            load_tile_s(BsP + st * 128 * SB, gB, SB, (kt + 2) * BK, tid);      \
            asm volatile("cp.async.commit_group;\n" ::);                       \
        }                                                                      \
        int cs = kt % 3;                                                       \
        CT(AsP + cs * 128 * SA, BsP + cs * 128 * SB, acc, wm, wn, gr, ctl);    \
    }

#define QKV_SMEM  (3 * 128 * SSI * 2 * 4)          // 73728 B
#define PROJ_SMEM (3 * 128 * (SSP + SSI) * 4)      // 67584 B

// ---------------------------------------------------------------------------
// QKV: y = x @ W^T + b, scattered into per-head (b,h,c,t,d), tf32-rounded.
// grid = (192, 12): y [0,4)=Q, [4,8)=K, [8,12)=V
// ---------------------------------------------------------------------------
__global__ void __launch_bounds__(256, 2)
qkv_mma(const float* __restrict__ bq, const float* __restrict__ bk,
        const float* __restrict__ bv)
{
    extern __shared__ float dsm_q[];
    float* As = dsm_q;                    // [3][128*SSI]
    float* Bs = dsm_q + 3 * 128 * SSI;    // [3][128*SSI]

    const int tid = threadIdx.x, lane = tid & 31, warp = tid >> 5;
    const int wm = warp & 1, wn = warp >> 1;
    const int gr = lane >> 2, ctl = lane & 3;

    const int m0 = blockIdx.x * 128;
    const int mm = blockIdx.y >> 2;
    const int f0 = (blockIdx.y & 3) * 128;

    const float* gA = g_xr + (size_t)m0 * En;
    const float* gB = g_wr + (size_t)mm * En * En + (size_t)f0 * En;
    const float* bias = (mm == 0) ? bq : (mm == 1) ? bk : bv;
    float* gout = (mm == 0) ? g_q : (mm == 1) ? g_k : g_v;

    float acc[4][4][4];
    #pragma unroll
    for (int i = 0; i < 4; i++)
        #pragma unroll
        for (int j = 0; j < 4; j++)
            #pragma unroll
            for (int l = 0; l < 4; l++) acc[i][j][l] = 0.f;

    GEMM_MAINLOOP3(gA, gB, SSI, SSI, compute_tile_ii, As, Bs)

    const int fbase = f0 + wn * 32;
    #pragma unroll
    for (int mi = 0; mi < 4; mi++) {
        #pragma unroll
        for (int half = 0; half < 2; half++) {
            int r = m0 + wm * 64 + mi * 16 + gr + half * 8;
            int b = r / (Tn * Cn);
            int rem = r - b * (Tn * Cn);
            int t = rem / Cn;
            int cc = rem - t * Cn;
            #pragma unroll
            for (int ni = 0; ni < 4; ni++) {
                int f = fbase + ni * 8 + 2 * ctl;
                int h = f >> 6, d = f & 63;
                float2 o;
                o.x = tf32r(acc[mi][ni][half * 2 + 0] + bias[f]);
                o.y = tf32r(acc[mi][ni][half * 2 + 1] + bias[f + 1]);
                float* dst = gout + ((((size_t)b * Hn + h) * Cn + cc) * Tn + t) * HD + d;
                *(float2*)dst = o;
            }
        }
    }
}

// ---------------------------------------------------------------------------
// Output projection: out = g_y(plain) @ Wp(interleaved)^T + bp.  grid=(192,4)
// ---------------------------------------------------------------------------
__global__ void __launch_bounds__(256, 2)
proj_mma(const float* __restrict__ bp, float* __restrict__ out)
{
    extern __shared__ float dsm_p[];
    float* As = dsm_p;                    // [3][128*SSP]
    float* Bs = dsm_p + 3 * 128 * SSP;    // [3][128*SSI]

    const int tid = threadIdx.x, lane = tid & 31, warp = tid >> 5;
    const int wm = warp & 1, wn = warp >> 1;
    const int gr = lane >> 2, ctl = lane & 3;

    const int m0 = blockIdx.x * 128;
    const int f0 = blockIdx.y * 128;

    const float* gA = g_y + (size_t)m0 * En;
    const float* gB = g_wr + (size_t)3 * En * En + (size_t)f0 * En;

    float acc[4][4][4];
    #pragma unroll
    for (int i = 0; i < 4; i++)
        #pragma unroll
        for (int j = 0; j < 4; j++)
            #pragma unroll
            for (int l = 0; l < 4; l++) acc[i][j][l] = 0.f;

    GEMM_MAINLOOP3(gA, gB, SSP, SSI, compute_tile_pi, As, Bs)

    #pragma unroll
    for (int mi = 0; mi < 4; mi++) {
        #pragma unroll
        for (int half = 0; half < 2; half++) {
            int r = m0 + wm * 64 + mi * 16 + gr + half * 8;
            #pragma unroll
            for (int ni = 0; ni < 4; ni++) {
                int col = f0 + wn * 32 + ni * 8 + 2 * ctl;
                float2 o;
                o.x = acc[mi][ni][half * 2 + 0] + bp[col];
                o.y = acc[mi][ni][half * 2 + 1] + bp[col + 1];
                *(float2*)(out + (size_t)r * En + col) = o;
            }
        }
    }
}

// ---------------------------------------------------------------------------
// MMA attention (round-4 structure, rna-rounded P, plain coalesced epilogue).
// 1 CTA per head, 8 warps; warp w owns query rows 32w..32w+31, does w/2+1 tiles.
// ---------------------------------------------------------------------------
#define KSTR 68
#define PSTR 72
#define ATTN_SMEM_BYTES ((2 * Tn * KSTR + 8 * 32 * PSTR) * 4)   // 212992

__global__ void __launch_bounds__(256, 1)
attn_kernel()
{
    extern __shared__ float smem[];
    float* Ks = smem;                  // [256][KSTR]
    float* Vs = smem + Tn * KSTR;      // [256][KSTR]

    const int hh = blockIdx.x;
    const int c  = hh % Cn;
    const int bh = hh / Cn;
    const int h  = bh % Hn;
    const int b  = bh / Hn;

    const float* qp = g_q + (size_t)hh * Tn * HD;
    const float* kp = g_k + (size_t)hh * Tn * HD;
    const float* vp = g_v + (size_t)hh * Tn * HD;

    const int tid  = threadIdx.x;
    const int lane = tid & 31, warp = tid >> 5;
    const int gr   = lane >> 2, ctl = lane & 3;

    float* Pw = smem + 2 * Tn * KSTR + warp * 32 * PSTR;  // [32][PSTR]

    // ---- load full K and V into smem ----
    #pragma unroll
    for (int it = 0; it < 16; it++) {
        int idx = it * 256 + tid;
        int row = idx >> 4;
        int c4  = (idx & 15) * 4;
        cpasync16(Ks + row * KSTR + c4, kp + row * HD + c4);
        cpasync16(Vs + row * KSTR + c4, vp + row * HD + c4);
    }
    asm volatile("cp.async.commit_group;\n" ::);

    const int r0 = warp * 32;
    asm volatile("cp.async.wait_group 0;\n" ::);
    __syncthreads();

    // ---- stage Q (scaled by exact 2^-3) into Pw, build A-fragments ----
    #pragma unroll
    for (int it = 0; it < 16; it++) {
        int idx = it * 32 + lane;
        int row = idx >> 4;
        int c4  = (idx & 15) * 4;
        float4 v4 = *(const float4*)(qp + (size_t)(r0 + row) * HD + c4);
        v4.x *= 0.125f; v4.y *= 0.125f; v4.z *= 0.125f; v4.w *= 0.125f;
        *(float4*)(Pw + row * PSTR + c4) = v4;
    }
    __syncwarp();

    uint32_t aq[2][8][4];
    #pragma unroll
    for (int mi = 0; mi < 2; mi++)
        #pragma unroll
        for (int ks = 0; ks < 8; ks++) {
            const float* p = Pw + (mi * 16 + gr) * PSTR + ks * 8 + ctl;
            aq[mi][ks][0] = __float_as_uint(p[0]);
            aq[mi][ks][1] = __float_as_uint(p[8 * PSTR]);
            aq[mi][ks][2] = __float_as_uint(p[4]);
            aq[mi][ks][3] = __float_as_uint(p[8 * PSTR + 4]);
        }

    float oacc[2][8][4];
    #pragma unroll
    for (int mi = 0; mi < 2; mi++)
        #pragma unroll
        for (int nt = 0; nt < 8; nt++)
            #pragma unroll
            for (int e = 0; e < 4; e++) oacc[mi][nt][e] = 0.f;
    float lsum[2][2] = {{0.f, 0.f}, {0.f, 0.f}};

    const int ntiles = (warp >> 1) + 1;

    #pragma unroll 1
    for (int jt = 0; jt < ntiles; jt++) {
        const int j0 = jt * 64;
        __syncwarp();

        #pragma unroll
        for (int hn = 0; hn < 2; hn++) {
            float s[2][4][4];
            #pragma unroll
            for (int mi = 0; mi < 2; mi++)
                #pragma unroll
                for (int n = 0; n < 4; n++)
                    #pragma unroll
                    for (int e = 0; e < 4; e++) s[mi][n][e] = 0.f;

            #pragma unroll
            for (int ks = 0; ks < 8; ks++) {
                uint32_t bfr[4][2];
                #pragma unroll
                for (int n = 0; n < 4; n++) {
                    const float* p = Ks + (j0 + (hn * 4 + n) * 8 + gr) * KSTR + ks * 8 + ctl;
                    bfr[n][0] = __float_as_uint(p[0]);
                    bfr[n][1] = __float_as_uint(p[4]);
                }
                #pragma unroll
                for (int mi = 0; mi < 2; mi++)
                    #pragma unroll
                    for (int n = 0; n < 4; n++)
                        mma_tf32(s[mi][n], aq[mi][ks], bfr[n]);
            }

            #pragma unroll
            for (int mi = 0; mi < 2; mi++) {
                const int rowb = r0 + mi * 16 + gr;
                #pragma unroll
                for (int n = 0; n < 4; n++) {
                    const int nt  = hn * 4 + n;
                    const int col = j0 + nt * 8 + 2 * ctl;
                    float p00 = (col     <= rowb)     ? tf32r(__expf(s[mi][n][0])) : 0.f;
                    float p01 = (col + 1 <= rowb)     ? tf32r(__expf(s[mi][n][1])) : 0.f;
                    float p10 = (col     <= rowb + 8) ? tf32r(__expf(s[mi][n][2])) : 0.f;
                    float p11 = (col + 1 <= rowb + 8) ? tf32r(__expf(s[mi][n][3])) : 0.f;
                    lsum[mi][0] += p00 + p01;
                    lsum[mi][1] += p10 + p11;
                    float2 v0 = {p00, p01}, v1 = {p10, p11};
                    *(float2*)(Pw + (mi * 16 + gr) * PSTR + nt * 8 + 2 * ctl)     = v0;
                    *(float2*)(Pw + (mi * 16 + 8 + gr) * PSTR + nt * 8 + 2 * ctl) = v1;
                }
            }
        }
        __syncwarp();

        #pragma unroll
        for (int ks = 0; ks < 8; ks++) {
            uint32_t ap[2][4];
            #pragma unroll
            for (int mi = 0; mi < 2; mi++) {
                const float* p = Pw + (mi * 16 + gr) * PSTR + ks * 8 + ctl;
                ap[mi][0] = __float_as_uint(p[0]);
                ap[mi][1] = __float_as_uint(p[8 * PSTR]);
                ap[mi][2] = __float_as_uint(p[4]);
                ap[mi][3] = __float_as_uint(p[8 * PSTR + 4]);
            }
            #pragma unroll
            for (int nt = 0; nt < 8; nt++) {
                uint32_t bv2[2];
                const float* p = Vs + (j0 + ks * 8 + ctl) * KSTR + nt * 8 + gr;
                bv2[0] = __float_as_uint(p[0]);
                bv2[1] = __float_as_uint(p[4 * KSTR]);
                #pragma unroll
                for (int mi = 0; mi < 2; mi++)
                    mma_tf32(oacc[mi][nt], ap[mi], bv2);
            }
        }
    }

    float inv[2][2];
    #pragma unroll
    for (int mi = 0; mi < 2; mi++)
        #pragma unroll
        for (int hf = 0; hf < 2; hf++) {
            float l = lsum[mi][hf];
            l += __shfl_xor_sync(0xffffffff, l, 1);
            l += __shfl_xor_sync(0xffffffff, l, 2);
            inv[mi][hf] = 1.f / l;
        }

    #pragma unroll
    for (int mi = 0; mi < 2; mi++)
        #pragma unroll
        for (int hf = 0; hf < 2; hf++) {
            int trow = r0 + mi * 16 + gr + 8 * hf;
            float* yp = g_y + (size_t)(b * Tn + trow) * (Hn * Cn * HD) + (h * Cn + c) * HD;
            #pragma unroll
            for (int nt = 0; nt < 8; nt++) {
                float2 o;
                o.x = tf32r(oacc[mi][nt][hf * 2 + 0] * inv[mi][hf]);
                o.y = tf32r(oacc[mi][nt][hf * 2 + 1] * inv[mi][hf]);
                *(float2*)(yp + nt * 8 + 2 * ctl) = o;
            }
        }
}

// ---------------------------------------------------------------------------
extern "C" void kernel_launch(void* const* d_in, const int* in_sizes, int n_in,
                              void* d_out, int out_size)
{
    const float* x  = (const float*)d_in[0];
    const float* Wq = (const float*)d_in[1];
    const float* bq = (const float*)d_in[2];
    const float* Wk = (const float*)d_in[3];
    const float* bk = (const float*)d_in[4];
    const float* Wv = (const float*)d_in[5];
    const float* bv = (const float*)d_in[6];
    const float* Wp = (const float*)d_in[7];
    const float* bp = (const float*)d_in[8];
    float* out = (float*)d_out;

    cudaFuncSetAttribute(qkv_mma,  cudaFuncAttributeMaxDynamicSharedMemorySize, QKV_SMEM);
    cudaFuncSetAttribute(proj_mma, cudaFuncAttributeMaxDynamicSharedMemorySize, PROJ_SMEM);
    cudaFuncSetAttribute(attn_kernel, cudaFuncAttributeMaxDynamicSharedMemorySize,
                         ATTN_SMEM_BYTES);

    round_all_kernel<<<(NX8 + NW8) / 256, 256>>>(x, Wq, Wk, Wv, Wp);
    qkv_mma<<<dim3(NTOK / 128, 12), 256, QKV_SMEM>>>(bq, bk, bv);
    attn_kernel<<<NHEADS, 256, ATTN_SMEM_BYTES>>>();
    proj_mma<<<dim3(NTOK / 128, 4), 256, PROJ_SMEM>>>(bp, out);
}

// round 16
// speedup vs baseline: 1.8645x; 1.8645x over previous
#include <cuda_runtime.h>
#include <cuda_fp16.h>
#include <cstdint>

#define Bn 16
#define Tn 256
#define Cn 6
#define En 512
#define Hn 8
#define HD 64
#define NTOK (Bn*Tn*Cn)      // 24576
#define NHEADS (Bn*Hn*Cn)    // 768

// ---- device-global scratch (no allocations allowed) ----
// g_xr, g_wr: fp16, k-pair-interleaved per 16-half block (pair order {0,4,1,5,2,6,3,7}).
// g_q/g_k/g_v/g_y: fp16, plain layout.
__device__ __half g_q[(size_t)NHEADS * Tn * HD];
__device__ __half g_k[(size_t)NHEADS * Tn * HD];
__device__ __half g_v[(size_t)NHEADS * Tn * HD];
__device__ __half g_y[(size_t)NTOK * En];
__device__ __half g_xr[(size_t)NTOK * En];
__device__ __half g_wr[(size_t)4 * En * En];

// ---------------------------------------------------------------------------
__device__ __forceinline__ uint32_t h2rn(float a, float b) {
    __half2 h = __floats2half2_rn(a, b);
    return *reinterpret_cast<uint32_t*>(&h);
}

__device__ __forceinline__ void cpasync16(void* smem_dst, const void* gsrc) {
    uint32_t s = (uint32_t)__cvta_generic_to_shared(smem_dst);
    asm volatile("cp.async.ca.shared.global [%0], [%1], 16;\n" :: "r"(s), "l"(gsrc));
}

__device__ __forceinline__ void mma_f16(float c[4], const uint32_t a[4], const uint32_t b[2]) {
    asm volatile(
        "mma.sync.aligned.m16n8k16.row.col.f32.f16.f16.f32 "
        "{%0,%1,%2,%3}, {%4,%5,%6,%7}, {%8,%9}, {%0,%1,%2,%3};"
        : "+f"(c[0]), "+f"(c[1]), "+f"(c[2]), "+f"(c[3])
        : "r"(a[0]), "r"(a[1]), "r"(a[2]), "r"(a[3]), "r"(b[0]), "r"(b[1]));
}

// ---------------------------------------------------------------------------
// Prepass: fp32 -> fp16(rn), pair-interleaved per 16-half k-block:
// out half order: k0,k1, k8,k9, k2,k3, k10,k11, k4,k5, k12,k13, k6,k7, k14,k15
// ---------------------------------------------------------------------------
#define NXB (NTOK * En / 16)     // 786432
#define NWB (4 * En * En / 16)   // 65536

__global__ void round_all_kernel(const float* __restrict__ x,
                                 const float* __restrict__ Wq, const float* __restrict__ Wk,
                                 const float* __restrict__ Wv, const float* __restrict__ Wp) {
    int i = blockIdx.x * 256 + threadIdx.x;
    const float* src;
    __half* dst;
    if (i < NXB) {
        src = x + (size_t)i * 16;
        dst = g_xr + (size_t)i * 16;
    } else {
        int j = i - NXB;
        int w = j >> 14;                 // 16384 blocks per weight matrix
        int off = j & 16383;
        src = ((w == 0) ? Wq : (w == 1) ? Wk : (w == 2) ? Wv : Wp) + (size_t)off * 16;
        dst = g_wr + (size_t)j * 16;
    }
    float4 v0 = ((const float4*)src)[0];
    float4 v1 = ((const float4*)src)[1];
    float4 v2 = ((const float4*)src)[2];
    float4 v3 = ((const float4*)src)[3];
    uint4 o0, o1;
    o0.x = h2rn(v0.x, v0.y);   // k0,k1
    o0.y = h2rn(v2.x, v2.y);   // k8,k9
    o0.z = h2rn(v0.z, v0.w);   // k2,k3
    o0.w = h2rn(v2.z, v2.w);   // k10,k11
    o1.x = h2rn(v1.x, v1.y);   // k4,k5
    o1.y = h2rn(v3.x, v3.y);   // k12,k13
    o1.z = h2rn(v1.z, v1.w);   // k6,k7
    o1.w = h2rn(v3.z, v3.w);   // k14,k15
    ((uint4*)dst)[0] = o0;
    ((uint4*)dst)[1] = o1;
}

// ---------------------------------------------------------------------------
// fp16 GEMM cores. 128x128 CTA tile, 8 warps (2M x 4N), warp tile 64x32,
// m16n8k16, BK=32 halves, double-buffered cp.async (round-12 proven loop).
//  - interleaved operand: stride 48 halves -> LDS.64 frags (CF verified)
//  - plain operand:       stride 40 halves -> LDS.32 frags (CF verified)
// ---------------------------------------------------------------------------
#define RSI 48
#define RSP 40
#define BKH 32
#define NKI (En / BKH)   // 16

__device__ __forceinline__ void load_tile_h(__half* dst, const __half* gsrc,
                                            int stride, int k0, int tid) {
    #pragma unroll
    for (int it = 0; it < 2; it++) {
        int idx = it * 256 + tid;       // 0..511 : 128 rows x 4 chunks of 8 halves
        int m   = idx >> 2;
        int kc  = idx & 3;
        cpasync16(dst + m * stride + kc * 8, gsrc + (size_t)m * En + k0 + kc * 8);
    }
}

// Both operands interleaved (qkv).
__device__ __forceinline__ void compute_tile_ii(const __half* As, const __half* Bs,
                                                float acc[4][4][4],
                                                int wm, int wn, int gr, int ctl) {
    #pragma unroll
    for (int ks = 0; ks < 2; ks++) {
        uint32_t a[4][4], b[4][2];
        #pragma unroll
        for (int mi = 0; mi < 4; mi++) {
            const __half* p = As + (wm * 64 + mi * 16 + gr) * RSI + ks * 16 + 4 * ctl;
            uint2 lo = *(const uint2*)p;              // pairs (2ctl, 2ctl+8) row r
            uint2 hi = *(const uint2*)(p + 8 * RSI);  // row r+8
            a[mi][0] = lo.x; a[mi][1] = hi.x; a[mi][2] = lo.y; a[mi][3] = hi.y;
        }
        #pragma unroll
        for (int ni = 0; ni < 4; ni++) {
            const __half* p = Bs + (wn * 32 + ni * 8 + gr) * RSI + ks * 16 + 4 * ctl;
            uint2 bb = *(const uint2*)p;
            b[ni][0] = bb.x; b[ni][1] = bb.y;
        }
        #pragma unroll
        for (int mi = 0; mi < 4; mi++)
            #pragma unroll
            for (int ni = 0; ni < 4; ni++)
                mma_f16(acc[mi][ni], a[mi], b[ni]);
    }
}

// A plain, B interleaved (proj).
__device__ __forceinline__ void compute_tile_pi(const __half* As, const __half* Bs,
                                                float acc[4][4][4],
                                                int wm, int wn, int gr, int ctl) {
    #pragma unroll
    for (int ks = 0; ks < 2; ks++) {
        uint32_t a[4][4], b[4][2];
        #pragma unroll
        for (int mi = 0; mi < 4; mi++) {
            const __half* p = As + (wm * 64 + mi * 16 + gr) * RSP + ks * 16 + 2 * ctl;
            a[mi][0] = *(const uint32_t*)p;
            a[mi][1] = *(const uint32_t*)(p + 8 * RSP);
            a[mi][2] = *(const uint32_t*)(p + 8);
            a[mi][3] = *(const uint32_t*)(p + 8 * RSP + 8);
        }
        #pragma unroll
        for (int ni = 0; ni < 4; ni++) {
            const __half* p = Bs + (wn * 32 + ni * 8 + gr) * RSI + ks * 16 + 4 * ctl;
            uint2 bb = *(const uint2*)p;
            b[ni][0] = bb.x; b[ni][1] = bb.y;
        }
        #pragma unroll
        for (int mi = 0; mi < 4; mi++)
            #pragma unroll
            for (int ni = 0; ni < 4; ni++)
                mma_f16(acc[mi][ni], a[mi], b[ni]);
    }
}

#define GEMM_MAINLOOP_H(gA, gB, SA, SB, CT, AsP, BsP)                          \
    load_tile_h(AsP, gA, SA, 0, tid);                                          \
    load_tile_h(BsP, gB, SB, 0, tid);                                          \
    asm volatile("cp.async.commit_group;\n" ::);                               \
    _Pragma("unroll 1")                                                        \
    for (int kt = 0; kt < NKI; kt++) {                                         \
        if (kt + 1 < NKI) {                                                    \
            load_tile_h(AsP + ((kt + 1) & 1) * 128 * SA, gA, SA, (kt + 1) * BKH, tid); \
            load_tile_h(BsP + ((kt + 1) & 1) * 128 * SB, gB, SB, (kt + 1) * BKH, tid); \
            asm volatile("cp.async.commit_group;\n" ::);                       \
            asm volatile("cp.async.wait_group 1;\n" ::);                       \
        } else {                                                               \
            asm volatile("cp.async.wait_group 0;\n" ::);                       \
        }                                                                      \
        __syncthreads();                                                       \
        CT(AsP + (kt & 1) * 128 * SA, BsP + (kt & 1) * 128 * SB, acc, wm, wn, gr, ctl); \
        __syncthreads();                                                       \
    }

#define QKV_SMEM  (2 * 128 * RSI * 2 * 2)                 // 49152 B
#define PROJ_SMEM ((2 * 128 * RSP + 2 * 128 * RSI) * 2)   // 45056 B

// ---------------------------------------------------------------------------
// QKV: y = x @ W^T + b -> per-head (b,h,c,t,d) fp16.  grid = (192, 12)
// ---------------------------------------------------------------------------
__global__ void __launch_bounds__(256, 2)
qkv_mma(const float* __restrict__ bq, const float* __restrict__ bk,
        const float* __restrict__ bv)
{
    extern __shared__ __half dsm_q[];
    __half* As = dsm_q;                    // [2][128*RSI]
    __half* Bs = dsm_q + 2 * 128 * RSI;

    const int tid = threadIdx.x, lane = tid & 31, warp = tid >> 5;
    const int wm = warp & 1, wn = warp >> 1;
    const int gr = lane >> 2, ctl = lane & 3;

    const int m0 = blockIdx.x * 128;
    const int mm = blockIdx.y >> 2;
    const int f0 = (blockIdx.y & 3) * 128;

    const __half* gA = g_xr + (size_t)m0 * En;
    const __half* gB = g_wr + (size_t)mm * En * En + (size_t)f0 * En;
    const float* bias = (mm == 0) ? bq : (mm == 1) ? bk : bv;
    __half* gout = (mm == 0) ? g_q : (mm == 1) ? g_k : g_v;

    float acc[4][4][4];
    #pragma unroll
    for (int i = 0; i < 4; i++)
        #pragma unroll
        for (int j = 0; j < 4; j++)
            #pragma unroll
            for (int l = 0; l < 4; l++) acc[i][j][l] = 0.f;

    GEMM_MAINLOOP_H(gA, gB, RSI, RSI, compute_tile_ii, As, Bs)

    const int fbase = f0 + wn * 32;
    #pragma unroll
    for (int mi = 0; mi < 4; mi++) {
        #pragma unroll
        for (int half = 0; half < 2; half++) {
            int r = m0 + wm * 64 + mi * 16 + gr + half * 8;
            int b = r / (Tn * Cn);
            int rem = r - b * (Tn * Cn);
            int t = rem / Cn;
            int cc = rem - t * Cn;
            #pragma unroll
            for (int ni = 0; ni < 4; ni++) {
                int f = fbase + ni * 8 + 2 * ctl;
                int h = f >> 6, d = f & 63;
                uint32_t o = h2rn(acc[mi][ni][half * 2 + 0] + bias[f],
                                  acc[mi][ni][half * 2 + 1] + bias[f + 1]);
                size_t idx = ((((size_t)b * Hn + h) * Cn + cc) * Tn + t) * HD + d;
                *(uint32_t*)(gout + idx) = o;
            }
        }
    }
}

// ---------------------------------------------------------------------------
// Output projection: out(f32) = g_y(f16 plain) @ Wp(f16 interleaved)^T + bp.
// ---------------------------------------------------------------------------
__global__ void __launch_bounds__(256, 2)
proj_mma(const float* __restrict__ bp, float* __restrict__ out)
{
    extern __shared__ __half dsm_p[];
    __half* As = dsm_p;                    // [2][128*RSP]
    __half* Bs = dsm_p + 2 * 128 * RSP;    // [2][128*RSI]

    const int tid = threadIdx.x, lane = tid & 31, warp = tid >> 5;
    const int wm = warp & 1, wn = warp >> 1;
    const int gr = lane >> 2, ctl = lane & 3;

    const int m0 = blockIdx.x * 128;
    const int f0 = blockIdx.y * 128;

    const __half* gA = g_y + (size_t)m0 * En;
    const __half* gB = g_wr + (size_t)3 * En * En + (size_t)f0 * En;

    float acc[4][4][4];
    #pragma unroll
    for (int i = 0; i < 4; i++)
        #pragma unroll
        for (int j = 0; j < 4; j++)
            #pragma unroll
            for (int l = 0; l < 4; l++) acc[i][j][l] = 0.f;

    GEMM_MAINLOOP_H(gA, gB, RSP, RSI, compute_tile_pi, As, Bs)

    #pragma unroll
    for (int mi = 0; mi < 4; mi++) {
        #pragma unroll
        for (int half = 0; half < 2; half++) {
            int r = m0 + wm * 64 + mi * 16 + gr + half * 8;
            #pragma unroll
            for (int ni = 0; ni < 4; ni++) {
                int col = f0 + wn * 32 + ni * 8 + 2 * ctl;
                float2 o;
                o.x = acc[mi][ni][half * 2 + 0] + bp[col];
                o.y = acc[mi][ni][half * 2 + 1] + bp[col + 1];
                *(float2*)(out + (size_t)r * En + col) = o;
            }
        }
    }
}

// ---------------------------------------------------------------------------
// fp16 MMA attention, register-resident P (C-frag pairs == A-frag k16 layout).
// 1 CTA per head, 8 warps; warp w owns rows 32w..32w+31, does w/2+1 KV tiles.
// K plain fp16 smem (full 64-half rows); V transposed fp16 smem; Q via LDG.
// Softmax scale folded post-MMA: p = exp(s * 0.125) (exact 2^-3).
// ---------------------------------------------------------------------------
#define RSK 72     // Ks row stride (halves): B-frag banks 4gr+ctl, CF
#define RSV 264    // VsT row stride (halves): B-frag banks 4gr+ctl, CF
#define ATTN_SMEM ((256 * RSK + 64 * RSV) * 2)   // 70656 B

__global__ void __launch_bounds__(256, 1)
attn_kernel()
{
    extern __shared__ __half smh[];
    __half* Ks = smh;                   // [256][RSK]
    __half* Vs = smh + 256 * RSK;       // [64][RSV]  (transposed: [d][s])

    const int hh = blockIdx.x;
    const int c  = hh % Cn;
    const int bh = hh / Cn;
    const int h  = bh % Hn;
    const int b  = bh / Hn;

    const __half* qp = g_q + (size_t)hh * Tn * HD;
    const __half* kp = g_k + (size_t)hh * Tn * HD;
    const __half* vp = g_v + (size_t)hh * Tn * HD;

    const int tid  = threadIdx.x;
    const int lane = tid & 31, warp = tid >> 5;
    const int gr   = lane >> 2, ctl = lane & 3;
    const int r0   = warp * 32;

    // ---- K: cp.async plain rows -- full row: 8 chunks x 8 halves ----
    #pragma unroll
    for (int it = 0; it < 8; it++) {
        int idx = it * 256 + tid;       // 0..2047 : 256 rows x 8 chunks
        int row = idx >> 3, kc = idx & 7;
        cpasync16(Ks + row * RSK + kc * 8, kp + row * HD + kc * 8);
    }
    asm volatile("cp.async.commit_group;\n" ::);

    // ---- V: transpose into Vs[d][s] (coalesced reads, scalar stores) ----
    const __half2* vp2 = (const __half2*)vp;
    #pragma unroll 4
    for (int it = 0; it < 32; it++) {
        int idx = it * 256 + tid;
        int dp = idx & 31;              // lane = dp -> 128B coalesced read
        int s  = idx >> 5;
        __half2 v = vp2[(size_t)s * 32 + dp];
        Vs[(2 * dp) * RSV + s]     = __low2half(v);
        Vs[(2 * dp + 1) * RSV + s] = __high2half(v);
    }

    // ---- Q A-fragments via direct LDG ----
    const uint32_t* qp32 = (const uint32_t*)qp;
    uint32_t aq[2][4][4];
    #pragma unroll
    for (int mi = 0; mi < 2; mi++)
        #pragma unroll
        for (int ks = 0; ks < 4; ks++) {
            int row = r0 + mi * 16 + gr;
            aq[mi][ks][0] = qp32[row * 32 + ks * 8 + ctl];
            aq[mi][ks][1] = qp32[(row + 8) * 32 + ks * 8 + ctl];
            aq[mi][ks][2] = qp32[row * 32 + ks * 8 + ctl + 4];
            aq[mi][ks][3] = qp32[(row + 8) * 32 + ks * 8 + ctl + 4];
        }

    asm volatile("cp.async.wait_group 0;\n" ::);
    __syncthreads();

    float oacc[2][8][4];
    #pragma unroll
    for (int mi = 0; mi < 2; mi++)
        #pragma unroll
        for (int dt = 0; dt < 8; dt++)
            #pragma unroll
            for (int e = 0; e < 4; e++) oacc[mi][dt][e] = 0.f;
    float lsum[2][2] = {{0.f, 0.f}, {0.f, 0.f}};

    const int ntiles = (warp >> 1) + 1;

    #pragma unroll 1
    for (int jt = 0; jt < ntiles; jt++) {
        const int j0 = jt * 64;
        #pragma unroll
        for (int ntp = 0; ntp < 4; ntp++) {       // 16-row s-block; PV kstep
            float s2[2][2][4];
            #pragma unroll
            for (int mi = 0; mi < 2; mi++)
                #pragma unroll
                for (int j = 0; j < 2; j++)
                    #pragma unroll
                    for (int e = 0; e < 4; e++) s2[mi][j][e] = 0.f;

            // S = Q @ K^T for n-tiles 2ntp, 2ntp+1
            #pragma unroll
            for (int ks = 0; ks < 4; ks++) {
                uint32_t bk2[2][2];
                #pragma unroll
                for (int j = 0; j < 2; j++) {
                    const uint32_t* kr = (const uint32_t*)
                        (Ks + (j0 + (ntp * 2 + j) * 8 + gr) * RSK + ks * 16);
                    bk2[j][0] = kr[ctl];
                    bk2[j][1] = kr[ctl + 4];
                }
                #pragma unroll
                for (int mi = 0; mi < 2; mi++)
                    #pragma unroll
                    for (int j = 0; j < 2; j++)
                        mma_f16(s2[mi][j], aq[mi][ks], bk2[j]);
            }

            // mask + exp + fp16 pack: C-frag pairs ARE the PV A-frag
            uint32_t ap[2][4];
            #pragma unroll
            for (int mi = 0; mi < 2; mi++) {
                const int row0 = r0 + mi * 16 + gr;
                #pragma unroll
                for (int j = 0; j < 2; j++) {
                    const int col = j0 + (ntp * 2 + j) * 8 + 2 * ctl;
                    float p00 = (col     <= row0)     ? __expf(s2[mi][j][0] * 0.125f) : 0.f;
                    float p01 = (col + 1 <= row0)     ? __expf(s2[mi][j][1] * 0.125f) : 0.f;
                    float p10 = (col     <= row0 + 8) ? __expf(s2[mi][j][2] * 0.125f) : 0.f;
                    float p11 = (col + 1 <= row0 + 8) ? __expf(s2[mi][j][3] * 0.125f) : 0.f;
                    uint32_t hlo = h2rn(p00, p01);
                    uint32_t hhi = h2rn(p10, p11);
                    ap[mi][j * 2 + 0] = hlo;      // row gr,  k-pair (2ctl, 2ctl+1)
                    ap[mi][j * 2 + 1] = hhi;      // row gr+8
                    float2 flo = __half22float2(*reinterpret_cast<__half2*>(&hlo));
                    float2 fhi = __half22float2(*reinterpret_cast<__half2*>(&hhi));
                    lsum[mi][0] += flo.x + flo.y;
                    lsum[mi][1] += fhi.x + fhi.y;
                }
            }

            // O += P @ V   (k-chunk = global s block j0 + ntp*16)
            #pragma unroll
            for (int dt = 0; dt < 8; dt++) {
                const uint32_t* vr = (const uint32_t*)
                    (Vs + (dt * 8 + gr) * RSV + j0 + ntp * 16);   // <-- +j0 FIX
                uint32_t bv[2];
                bv[0] = vr[ctl];
                bv[1] = vr[ctl + 4];
                #pragma unroll
                for (int mi = 0; mi < 2; mi++)
                    mma_f16(oacc[mi][dt], ap[mi], bv);
            }
        }
    }

    // ---- reduce lsum over ctl group, normalize, write g_y fp16 ----
    float inv[2][2];
    #pragma unroll
    for (int mi = 0; mi < 2; mi++)
        #pragma unroll
        for (int hf = 0; hf < 2; hf++) {
            float l = lsum[mi][hf];
            l += __shfl_xor_sync(0xffffffff, l, 1);
            l += __shfl_xor_sync(0xffffffff, l, 2);
            inv[mi][hf] = 1.f / l;
        }

    #pragma unroll
    for (int mi = 0; mi < 2; mi++)
        #pragma unroll
        for (int hf = 0; hf < 2; hf++) {
            int trow = r0 + mi * 16 + gr + 8 * hf;
            uint32_t* yp = (uint32_t*)g_y
                + (size_t)(b * Tn + trow) * 1536 + (h * Cn + c) * 32;
            #pragma unroll
            for (int dt = 0; dt < 8; dt++)
                yp[dt * 4 + ctl] = h2rn(oacc[mi][dt][hf * 2 + 0] * inv[mi][hf],
                                        oacc[mi][dt][hf * 2 + 1] * inv[mi][hf]);
        }
}

// ---------------------------------------------------------------------------
extern "C" void kernel_launch(void* const* d_in, const int* in_sizes, int n_in,
                              void* d_out, int out_size)
{
    const float* x  = (const float*)d_in[0];
    const float* Wq = (const float*)d_in[1];
    const float* bq = (const float*)d_in[2];
    const float* Wk = (const float*)d_in[3];
    const float* bk = (const float*)d_in[4];
    const float* Wv = (const float*)d_in[5];
    const float* bv = (const float*)d_in[6];
    const float* Wp = (const float*)d_in[7];
    const float* bp = (const float*)d_in[8];
    float* out = (float*)d_out;

    cudaFuncSetAttribute(qkv_mma,  cudaFuncAttributeMaxDynamicSharedMemorySize, QKV_SMEM);
    cudaFuncSetAttribute(proj_mma, cudaFuncAttributeMaxDynamicSharedMemorySize, PROJ_SMEM);
    cudaFuncSetAttribute(attn_kernel, cudaFuncAttributeMaxDynamicSharedMemorySize, ATTN_SMEM);

    round_all_kernel<<<(NXB + NWB) / 256, 256>>>(x, Wq, Wk, Wv, Wp);
    qkv_mma<<<dim3(NTOK / 128, 12), 256, QKV_SMEM>>>(bq, bk, bv);
    attn_kernel<<<NHEADS, 256, ATTN_SMEM>>>();
    proj_mma<<<dim3(NTOK / 128, 4), 256, PROJ_SMEM>>>(bp, out);
}